// round 1
// baseline (speedup 1.0000x reference)
#include <cuda_runtime.h>
#include <math.h>

#define EPS 1e-5f

// Problem dims
#define BSZ   1024
#define EDIM  200
#define NE_   50000
#define OCFW  288     // 32*9
#define FCIN  6144    // 32*192
#define SPLITK 8
#define KCH3  (FCIN / SPLITK)  // 768

// ---------------- scratch (static device allocations are allowed) ----------
__device__ float g_cat [BSZ * 400];        // [B, 2E] concat(es, ec)
__device__ float g_rg  [BSZ * EDIM];       // gathered relation
__device__ float g_x   [BSZ * EDIM];       // bn0 output
__device__ float g_k   [BSZ * OCFW];       // dynamic filters
__device__ float g_flat[BSZ * FCIN];       // conv output flattened (25 MB)
__device__ float g_part[SPLITK * BSZ * EDIM]; // split-K partials
__device__ float g_h   [BSZ * EDIM];       // relu(bn2(fc)) output

// ---------------- f32x2 packed math ----------------------------------------
typedef unsigned long long ull;

__device__ __forceinline__ ull pk2(float lo, float hi) {
    ull r;
    asm("mov.b64 %0, {%1, %2};" : "=l"(r) : "f"(lo), "f"(hi));
    return r;
}
__device__ __forceinline__ float2 upk2(ull v) {
    float lo, hi;
    asm("mov.b64 {%0, %1}, %2;" : "=f"(lo), "=f"(hi) : "l"(v));
    return make_float2(lo, hi);
}
__device__ __forceinline__ void fma2(ull &d, ull a, ull b) {
    asm("fma.rn.f32x2 %0, %1, %2, %0;" : "+l"(d) : "l"(a), "l"(b));
}

// ---------------- gather ----------------------------------------------------
__global__ void gather_kernel(const int* __restrict__ e_s,
                              const int* __restrict__ q_s,
                              const int* __restrict__ e_c,
                              const float* __restrict__ ent,
                              const float* __restrict__ rel) {
    int b = blockIdx.x;
    int s = e_s[b], c = e_c[b], q = q_s[b];
    for (int j = threadIdx.x; j < EDIM; j += blockDim.x) {
        g_cat[b * 400 + j]        = ent[(size_t)s * EDIM + j];
        g_cat[b * 400 + EDIM + j] = ent[(size_t)c * EDIM + j];
        g_rg [b * EDIM + j]       = rel[(size_t)q * EDIM + j];
    }
}

// ---------------- generic tiled SGEMM (f32x2), 128x128x8, 8x8 thread tile ---
// C = A[M,K] @ B  (+ epilogue).  BTRANS=false: B is [K,N] row-major.
//                                BTRANS=true : B is [N,K] row-major (B^T view).
// MODE 0: bn0 epilogue (scalar bn): out = (v + bias[n] - m)*g/sqrt(v0+eps) + b
// MODE 1: out = v + bias[n]
// MODE 2: out = v (split-K partial, offset by blockIdx.z*M rows)
// MODE 3: out = sigmoid(v + bias[n])
template<int MODE, bool BTRANS>
__global__ __launch_bounds__(256)
void gemm128(const float* __restrict__ A, const float* __restrict__ Bm,
             float* __restrict__ C, int M, int N, int K,
             int kchunk, int ldc,
             const float* __restrict__ bias,
             const float* __restrict__ p0, const float* __restrict__ p1,
             const float* __restrict__ p2, const float* __restrict__ p3) {
    const int BM = 128, BN = 128, BK = 8, STR = 132; // padded stride
    __shared__ float As[BK * STR];
    __shared__ float Bs[BK * STR];

    const int tid = threadIdx.x;
    const int tx = tid & 15;        // n direction
    const int ty = tid >> 4;        // m direction
    const int m0 = blockIdx.y * BM;
    const int n0 = blockIdx.x * BN;
    const int k0 = blockIdx.z * kchunk;

    ull acc[8][4];
#pragma unroll
    for (int i = 0; i < 8; i++)
#pragma unroll
        for (int j = 0; j < 4; j++) acc[i][j] = 0ULL;

    for (int kb = k0; kb < k0 + kchunk; kb += BK) {
        // ---- load A tile: 128 rows x 8 k, float4 along k, transpose to As[k][m]
        {
            int m  = tid >> 1;
            int kq = (tid & 1) * 4;
            float4 av = *(const float4*)(A + (size_t)(m0 + m) * K + kb + kq);
            As[(kq + 0) * STR + m] = av.x;
            As[(kq + 1) * STR + m] = av.y;
            As[(kq + 2) * STR + m] = av.z;
            As[(kq + 3) * STR + m] = av.w;
        }
        // ---- load B tile
        if (!BTRANS) {
            int kk = tid >> 5;
            int n  = (tid & 31) * 4;
            float4 bv = make_float4(0.f, 0.f, 0.f, 0.f);
            if (n0 + n < N)
                bv = *(const float4*)(Bm + (size_t)(kb + kk) * N + n0 + n);
            *(float4*)(&Bs[kk * STR + n]) = bv;
        } else {
            int n  = tid >> 1;
            int kq = (tid & 1) * 4;
            float4 bv = make_float4(0.f, 0.f, 0.f, 0.f);
            if (n0 + n < N)
                bv = *(const float4*)(Bm + (size_t)(n0 + n) * K + kb + kq);
            Bs[(kq + 0) * STR + n] = bv.x;
            Bs[(kq + 1) * STR + n] = bv.y;
            Bs[(kq + 2) * STR + n] = bv.z;
            Bs[(kq + 3) * STR + n] = bv.w;
        }
        __syncthreads();

#pragma unroll
        for (int kk = 0; kk < BK; kk++) {
            const float* arow = &As[kk * STR + ty * 8];
            const float* brow = &Bs[kk * STR + tx * 8];
            float4 a0 = *(const float4*)(arow);
            float4 a1 = *(const float4*)(arow + 4);
            ull bp0 = *(const ull*)(brow + 0);
            ull bp1 = *(const ull*)(brow + 2);
            ull bp2 = *(const ull*)(brow + 4);
            ull bp3 = *(const ull*)(brow + 6);
            float am[8] = {a0.x, a0.y, a0.z, a0.w, a1.x, a1.y, a1.z, a1.w};
#pragma unroll
            for (int i = 0; i < 8; i++) {
                ull ap = pk2(am[i], am[i]);
                fma2(acc[i][0], ap, bp0);
                fma2(acc[i][1], ap, bp1);
                fma2(acc[i][2], ap, bp2);
                fma2(acc[i][3], ap, bp3);
            }
        }
        __syncthreads();
    }

    // ---- epilogue ----
    float sc0 = 1.f, sm0 = 0.f, sb0 = 0.f;
    if (MODE == 0) {
        sc0 = p0[0] * rsqrtf(p1[0] + EPS);
        sm0 = p2[0];
        sb0 = p3[0];
    }
    size_t rowbase = (size_t)blockIdx.z * M; // 0 unless split-K partial
#pragma unroll
    for (int i = 0; i < 8; i++) {
        int m = m0 + ty * 8 + i;
        float* crow = C + (rowbase + m) * (size_t)ldc;
#pragma unroll
        for (int j = 0; j < 4; j++) {
            float2 v = upk2(acc[i][j]);
            int n = n0 + tx * 8 + j * 2;
            float vs[2] = {v.x, v.y};
#pragma unroll
            for (int l = 0; l < 2; l++) {
                int nn = n + l;
                if (nn < N) {
                    float val = vs[l];
                    if (MODE == 0) val = (val + bias[nn] - sm0) * sc0 + sb0;
                    else if (MODE == 1) val = val + bias[nn];
                    else if (MODE == 3) val = 1.f / (1.f + expf(-(val + bias[nn])));
                    crow[nn] = val;
                }
            }
        }
    }
}

// ---------------- per-sample dynamic conv + bn1 -----------------------------
__global__ void conv_kernel(const float* __restrict__ bn1_g,
                            const float* __restrict__ bn1_b,
                            const float* __restrict__ bn1_m,
                            const float* __restrict__ bn1_v) {
    int b = blockIdx.x;
    __shared__ float xs[EDIM];
    __shared__ float ks[OCFW];
    __shared__ float sc[32], sh[32];
    int t = threadIdx.x; // 192 threads
    for (int j = t; j < EDIM; j += 192) xs[j] = g_x[b * EDIM + j];
    for (int j = t; j < OCFW; j += 192) ks[j] = g_k[b * OCFW + j];
    if (t < 32) {
        float s = bn1_g[t] * rsqrtf(bn1_v[t] + EPS);
        sc[t] = s;
        sh[t] = bn1_b[t] - bn1_m[t] * s;
    }
    __syncthreads();
    int p = t; // 0..191
    float xv[9];
#pragma unroll
    for (int w = 0; w < 9; w++) xv[w] = xs[p + w];
    float* outrow = &g_flat[(size_t)b * FCIN];
#pragma unroll 4
    for (int oc = 0; oc < 32; oc++) {
        float s = 0.f;
#pragma unroll
        for (int w = 0; w < 9; w++) s += xv[w] * ks[oc * 9 + w];
        outrow[oc * 192 + p] = s * sc[oc] + sh[oc];
    }
}

// ---------------- split-K reduce + fc bias + bn2 + relu ---------------------
__global__ void reduce_kernel(const float* __restrict__ fc_b,
                              const float* __restrict__ g2,
                              const float* __restrict__ b2,
                              const float* __restrict__ m2,
                              const float* __restrict__ v2) {
    int idx = blockIdx.x * 256 + threadIdx.x;
    if (idx >= BSZ * EDIM) return;
    int n = idx % EDIM;
    float s = fc_b[n];
#pragma unroll
    for (int z = 0; z < SPLITK; z++) s += g_part[(size_t)z * BSZ * EDIM + idx];
    float sc = g2[n] * rsqrtf(v2[n] + EPS);
    s = (s - m2[n]) * sc + b2[n];
    g_h[idx] = fmaxf(s, 0.f);
}

// ---------------- launch -----------------------------------------------------
static float* sym_addr(const void* sym) {
    void* p = nullptr;
    cudaGetSymbolAddress(&p, sym);
    return (float*)p;
}

extern "C" void kernel_launch(void* const* d_in, const int* in_sizes, int n_in,
                              void* d_out, int out_size) {
    const int*   e_s    = (const int*)d_in[0];
    const int*   q_s    = (const int*)d_in[1];
    const int*   e_c    = (const int*)d_in[2];
    const float* ent    = (const float*)d_in[3];
    const float* rel    = (const float*)d_in[4];
    const float* W1_w   = (const float*)d_in[5];
    const float* W1_b   = (const float*)d_in[6];
    const float* fc1_w  = (const float*)d_in[7];
    const float* fc1_b  = (const float*)d_in[8];
    const float* fc_w   = (const float*)d_in[9];
    const float* fc_b   = (const float*)d_in[10];
    const float* bn0_g  = (const float*)d_in[11];
    const float* bn0_b  = (const float*)d_in[12];
    const float* bn0_m  = (const float*)d_in[13];
    const float* bn0_v  = (const float*)d_in[14];
    const float* bn1_g  = (const float*)d_in[15];
    const float* bn1_b  = (const float*)d_in[16];
    const float* bn1_m  = (const float*)d_in[17];
    const float* bn1_v  = (const float*)d_in[18];
    const float* bn2_g  = (const float*)d_in[19];
    const float* bn2_b  = (const float*)d_in[20];
    const float* bn2_m  = (const float*)d_in[21];
    const float* bn2_v  = (const float*)d_in[22];
    const float* bias_b = (const float*)d_in[23];
    float* out = (float*)d_out;

    float* p_cat  = sym_addr(g_cat);
    float* p_rg   = sym_addr(g_rg);
    float* p_x    = sym_addr(g_x);
    float* p_k    = sym_addr(g_k);
    float* p_flat = sym_addr(g_flat);
    float* p_part = sym_addr(g_part);
    float* p_h    = sym_addr(g_h);

    // 1) gather embeddings
    gather_kernel<<<BSZ, 256>>>(e_s, q_s, e_c, ent, rel);

    // 2) e1 = cat @ W1 + b, bn0 -> g_x   (M=1024, N=200, K=400)
    {
        dim3 g(2, 8, 1);
        gemm128<0, false><<<g, 256>>>(p_cat, W1_w, p_x, BSZ, EDIM, 400,
                                      400, EDIM, W1_b, bn0_g, bn0_v, bn0_m, bn0_b);
    }
    // 3) k = r @ fc1_w + b -> g_k        (M=1024, N=288, K=200)
    {
        dim3 g(3, 8, 1);
        gemm128<1, false><<<g, 256>>>(p_rg, fc1_w, p_k, BSZ, OCFW, EDIM,
                                      EDIM, OCFW, fc1_b, nullptr, nullptr, nullptr, nullptr);
    }
    // 4) per-sample conv + bn1 -> g_flat
    conv_kernel<<<BSZ, 192>>>(bn1_g, bn1_b, bn1_m, bn1_v);

    // 5) split-K partials of flat @ fc_w (M=1024, N=200, K=6144, 8-way split)
    {
        dim3 g(2, 8, SPLITK);
        gemm128<2, false><<<g, 256>>>(p_flat, fc_w, p_part, BSZ, EDIM, FCIN,
                                      KCH3, EDIM, nullptr, nullptr, nullptr, nullptr, nullptr);
    }
    // 6) reduce + fc_b + bn2 + relu -> g_h
    reduce_kernel<<<(BSZ * EDIM + 255) / 256, 256>>>(fc_b, bn2_g, bn2_b, bn2_m, bn2_v);

    // 7) logits = h @ ent^T + bias_b, sigmoid -> out  (M=1024, N=50000, K=200)
    {
        dim3 g((NE_ + 127) / 128, 8, 1);
        gemm128<3, true><<<g, 256>>>(p_h, ent, out, BSZ, NE_, EDIM,
                                     EDIM, NE_, bias_b, nullptr, nullptr, nullptr, nullptr);
    }
}

// round 2
// speedup vs baseline: 1.7721x; 1.7721x over previous
#include <cuda_runtime.h>
#include <cuda_bf16.h>
#include <math.h>

#define EPS 1e-5f

// Problem dims
#define BSZ   1024
#define EDIM  200
#define NE_   50000
#define OCFW  288     // 32*9
#define FCIN  6144    // 32*192
#define SPLITK 8
#define KCH3  (FCIN / SPLITK)  // 768

#define KP    208     // K padded to 13*16 for bf16 mma
#define LDA   216     // smem row stride (bf16 elems) - conflict-free ldmatrix

// ---------------- scratch --------------------------------------------------
__device__ float g_cat [BSZ * 400];
__device__ float g_rg  [BSZ * EDIM];
__device__ float g_x   [BSZ * EDIM];
__device__ float g_k   [BSZ * OCFW];
__device__ float g_flat[BSZ * FCIN];
__device__ float g_part[SPLITK * BSZ * EDIM];
__device__ __nv_bfloat16 g_h_bf [BSZ * KP];
__device__ __nv_bfloat16 g_ent_bf[(size_t)NE_ * KP];   // ~20.8 MB, fits L2

// ---------------- f32x2 packed math (for small GEMMs) ----------------------
typedef unsigned long long ull;

__device__ __forceinline__ ull pk2(float lo, float hi) {
    ull r; asm("mov.b64 %0, {%1, %2};" : "=l"(r) : "f"(lo), "f"(hi)); return r;
}
__device__ __forceinline__ float2 upk2(ull v) {
    float lo, hi; asm("mov.b64 {%0, %1}, %2;" : "=f"(lo), "=f"(hi) : "l"(v));
    return make_float2(lo, hi);
}
__device__ __forceinline__ void fma2(ull &d, ull a, ull b) {
    asm("fma.rn.f32x2 %0, %1, %2, %0;" : "+l"(d) : "l"(a), "l"(b));
}

// ---------------- tensor-core helpers ---------------------------------------
__device__ __forceinline__ void ldsm_x4(unsigned* r, const __nv_bfloat16* p) {
    unsigned addr = (unsigned)__cvta_generic_to_shared(p);
    asm volatile("ldmatrix.sync.aligned.m8n8.x4.shared.b16 {%0,%1,%2,%3}, [%4];"
                 : "=r"(r[0]), "=r"(r[1]), "=r"(r[2]), "=r"(r[3]) : "r"(addr));
}
__device__ __forceinline__ void mma_bf16(float* c, const unsigned* a, const unsigned* b) {
    asm volatile("mma.sync.aligned.m16n8k16.row.col.f32.bf16.bf16.f32 "
                 "{%0,%1,%2,%3},{%4,%5,%6,%7},{%8,%9},{%0,%1,%2,%3};"
                 : "+f"(c[0]), "+f"(c[1]), "+f"(c[2]), "+f"(c[3])
                 : "r"(a[0]), "r"(a[1]), "r"(a[2]), "r"(a[3]),
                   "r"(b[0]), "r"(b[1]));
}

// ---------------- gather ----------------------------------------------------
__global__ void gather_kernel(const int* __restrict__ e_s,
                              const int* __restrict__ q_s,
                              const int* __restrict__ e_c,
                              const float* __restrict__ ent,
                              const float* __restrict__ rel) {
    int b = blockIdx.x;
    int s = e_s[b], c = e_c[b], q = q_s[b];
    for (int j = threadIdx.x; j < EDIM; j += blockDim.x) {
        g_cat[b * 400 + j]        = ent[(size_t)s * EDIM + j];
        g_cat[b * 400 + EDIM + j] = ent[(size_t)c * EDIM + j];
        g_rg [b * EDIM + j]       = rel[(size_t)q * EDIM + j];
    }
}

// ---------------- entity table fp32 -> bf16 (padded) ------------------------
__global__ void ent2bf_kernel(const float* __restrict__ ent) {
    int r = blockIdx.x;
    int c = threadIdx.x;                       // 208 threads
    float v = (c < EDIM) ? ent[(size_t)r * EDIM + c] : 0.f;
    g_ent_bf[(size_t)r * KP + c] = __float2bfloat16(v);
}

// ---------------- generic tiled SGEMM (f32x2), small GEMMs ------------------
// MODE 0: bn0 epilogue; MODE 1: +bias; MODE 2: split-K partial
template<int MODE, bool BTRANS>
__global__ __launch_bounds__(256)
void gemm128(const float* __restrict__ A, const float* __restrict__ Bm,
             float* __restrict__ C, int M, int N, int K,
             int kchunk, int ldc,
             const float* __restrict__ bias,
             const float* __restrict__ p0, const float* __restrict__ p1,
             const float* __restrict__ p2, const float* __restrict__ p3) {
    const int BM = 128, BK = 8, STR = 132;
    __shared__ float As[BK * STR];
    __shared__ float Bs[BK * STR];

    const int tid = threadIdx.x;
    const int tx = tid & 15;
    const int ty = tid >> 4;
    const int m0 = blockIdx.y * BM;
    const int n0 = blockIdx.x * 128;
    const int k0 = blockIdx.z * kchunk;

    ull acc[8][4];
#pragma unroll
    for (int i = 0; i < 8; i++)
#pragma unroll
        for (int j = 0; j < 4; j++) acc[i][j] = 0ULL;

    for (int kb = k0; kb < k0 + kchunk; kb += BK) {
        {
            int m  = tid >> 1;
            int kq = (tid & 1) * 4;
            float4 av = *(const float4*)(A + (size_t)(m0 + m) * K + kb + kq);
            As[(kq + 0) * STR + m] = av.x;
            As[(kq + 1) * STR + m] = av.y;
            As[(kq + 2) * STR + m] = av.z;
            As[(kq + 3) * STR + m] = av.w;
        }
        if (!BTRANS) {
            int kk = tid >> 5;
            int n  = (tid & 31) * 4;
            float4 bv = make_float4(0.f, 0.f, 0.f, 0.f);
            if (n0 + n < N)
                bv = *(const float4*)(Bm + (size_t)(kb + kk) * N + n0 + n);
            *(float4*)(&Bs[kk * STR + n]) = bv;
        } else {
            int n  = tid >> 1;
            int kq = (tid & 1) * 4;
            float4 bv = make_float4(0.f, 0.f, 0.f, 0.f);
            if (n0 + n < N)
                bv = *(const float4*)(Bm + (size_t)(n0 + n) * K + kb + kq);
            Bs[(kq + 0) * STR + n] = bv.x;
            Bs[(kq + 1) * STR + n] = bv.y;
            Bs[(kq + 2) * STR + n] = bv.z;
            Bs[(kq + 3) * STR + n] = bv.w;
        }
        __syncthreads();

#pragma unroll
        for (int kk = 0; kk < BK; kk++) {
            const float* arow = &As[kk * STR + ty * 8];
            const float* brow = &Bs[kk * STR + tx * 8];
            float4 a0 = *(const float4*)(arow);
            float4 a1 = *(const float4*)(arow + 4);
            ull bp0 = *(const ull*)(brow + 0);
            ull bp1 = *(const ull*)(brow + 2);
            ull bp2 = *(const ull*)(brow + 4);
            ull bp3 = *(const ull*)(brow + 6);
            float am[8] = {a0.x, a0.y, a0.z, a0.w, a1.x, a1.y, a1.z, a1.w};
#pragma unroll
            for (int i = 0; i < 8; i++) {
                ull ap = pk2(am[i], am[i]);
                fma2(acc[i][0], ap, bp0);
                fma2(acc[i][1], ap, bp1);
                fma2(acc[i][2], ap, bp2);
                fma2(acc[i][3], ap, bp3);
            }
        }
        __syncthreads();
    }

    float sc0 = 1.f, sm0 = 0.f, sb0 = 0.f;
    if (MODE == 0) {
        sc0 = p0[0] * rsqrtf(p1[0] + EPS);
        sm0 = p2[0];
        sb0 = p3[0];
    }
    size_t rowbase = (size_t)blockIdx.z * M;
#pragma unroll
    for (int i = 0; i < 8; i++) {
        int m = m0 + ty * 8 + i;
        float* crow = C + (rowbase + m) * (size_t)ldc;
#pragma unroll
        for (int j = 0; j < 4; j++) {
            float2 v = upk2(acc[i][j]);
            int n = n0 + tx * 8 + j * 2;
            float vs[2] = {v.x, v.y};
#pragma unroll
            for (int l = 0; l < 2; l++) {
                int nn = n + l;
                if (nn < N) {
                    float val = vs[l];
                    if (MODE == 0) val = (val + bias[nn] - sm0) * sc0 + sb0;
                    else if (MODE == 1) val = val + bias[nn];
                    crow[nn] = val;
                }
            }
        }
    }
}

// ---------------- per-sample dynamic conv + bn1 -----------------------------
__global__ void conv_kernel(const float* __restrict__ bn1_g,
                            const float* __restrict__ bn1_b,
                            const float* __restrict__ bn1_m,
                            const float* __restrict__ bn1_v) {
    int b = blockIdx.x;
    __shared__ float xs[EDIM];
    __shared__ float ks[OCFW];
    __shared__ float sc[32], sh[32];
    int t = threadIdx.x; // 192 threads
    for (int j = t; j < EDIM; j += 192) xs[j] = g_x[b * EDIM + j];
    for (int j = t; j < OCFW; j += 192) ks[j] = g_k[b * OCFW + j];
    if (t < 32) {
        float s = bn1_g[t] * rsqrtf(bn1_v[t] + EPS);
        sc[t] = s;
        sh[t] = bn1_b[t] - bn1_m[t] * s;
    }
    __syncthreads();
    int p = t;
    float xv[9];
#pragma unroll
    for (int w = 0; w < 9; w++) xv[w] = xs[p + w];
    float* outrow = &g_flat[(size_t)b * FCIN];
#pragma unroll 4
    for (int oc = 0; oc < 32; oc++) {
        float s = 0.f;
#pragma unroll
        for (int w = 0; w < 9; w++) s += xv[w] * ks[oc * 9 + w];
        outrow[oc * 192 + p] = s * sc[oc] + sh[oc];
    }
}

// ---------------- split-K reduce + fc bias + bn2 + relu -> bf16 h -----------
__global__ void reduce_kernel(const float* __restrict__ fc_b,
                              const float* __restrict__ g2,
                              const float* __restrict__ b2,
                              const float* __restrict__ m2,
                              const float* __restrict__ v2) {
    int b = blockIdx.x;
    int n = threadIdx.x;       // 208 threads, last 8 are zero pad
    float r = 0.f;
    if (n < EDIM) {
        float s = fc_b[n];
        int idx = b * EDIM + n;
#pragma unroll
        for (int z = 0; z < SPLITK; z++) s += g_part[(size_t)z * BSZ * EDIM + idx];
        float sc = g2[n] * rsqrtf(v2[n] + EPS);
        s = (s - m2[n]) * sc + b2[n];
        r = fmaxf(s, 0.f);
    }
    g_h_bf[b * KP + n] = __float2bfloat16(r);
}

// ---------------- GEMM4: logits = h @ ent^T + bias, sigmoid (tensor core) ---
// C[1024, 50000] = A[1024, KP]_bf16 @ B[50000, KP]_bf16^T
// CTA tile 128x128, full K resident. 8 warps = 4(M) x 2(N), warp tile 32x64.
__global__ __launch_bounds__(256)
void gemm4_tc(const float* __restrict__ bias, float* __restrict__ out) {
    extern __shared__ __nv_bfloat16 smem[];
    __nv_bfloat16* As = smem;
    __nv_bfloat16* Bs = smem + 128 * LDA;

    const int tid = threadIdx.x;
    const int m0 = blockIdx.y * 128;
    const int n0 = blockIdx.x * 128;

    // ---- stage A (h) tile: 128 x 208 bf16
    for (int i = tid; i < 128 * 26; i += 256) {
        int r = i / 26, c = (i % 26) * 8;
        uint4 v = *(const uint4*)(g_h_bf + (size_t)(m0 + r) * KP + c);
        *(uint4*)(As + r * LDA + c) = v;
    }
    // ---- stage B (entity) tile: 128 x 208 bf16, guarded
    for (int i = tid; i < 128 * 26; i += 256) {
        int r = i / 26, c = (i % 26) * 8;
        uint4 v = make_uint4(0u, 0u, 0u, 0u);
        if (n0 + r < NE_)
            v = *(const uint4*)(g_ent_bf + (size_t)(n0 + r) * KP + c);
        *(uint4*)(Bs + r * LDA + c) = v;
    }
    __syncthreads();

    const int wid  = tid >> 5;
    const int lane = tid & 31;
    const int wm = (wid & 3) * 32;   // warp M offset within tile
    const int wn = (wid >> 2) * 64;  // warp N offset within tile

    float acc[2][8][4];
#pragma unroll
    for (int i = 0; i < 2; i++)
#pragma unroll
        for (int j = 0; j < 8; j++)
#pragma unroll
            for (int l = 0; l < 4; l++) acc[i][j][l] = 0.f;

#pragma unroll
    for (int ks = 0; ks < 13; ks++) {
        const int k0 = ks * 16;
        unsigned a[2][4];
#pragma unroll
        for (int mi = 0; mi < 2; mi++) {
            int row = wm + mi * 16 + (lane & 15);
            ldsm_x4(a[mi], &As[row * LDA + k0 + (lane >> 4) * 8]);
        }
        unsigned b[8][2];
#pragma unroll
        for (int nj = 0; nj < 4; nj++) {
            int row = wn + nj * 16 + ((lane >> 4) & 1) * 8 + (lane & 7);
            int ko  = k0 + ((lane >> 3) & 1) * 8;
            unsigned t[4];
            ldsm_x4(t, &Bs[row * LDA + ko]);
            b[2 * nj    ][0] = t[0]; b[2 * nj    ][1] = t[1];
            b[2 * nj + 1][0] = t[2]; b[2 * nj + 1][1] = t[3];
        }
#pragma unroll
        for (int mi = 0; mi < 2; mi++)
#pragma unroll
            for (int ni = 0; ni < 8; ni++)
                mma_bf16(acc[mi][ni], a[mi], b[ni]);
    }

    // ---- epilogue: + bias, sigmoid, store
#pragma unroll
    for (int mi = 0; mi < 2; mi++) {
#pragma unroll
        for (int ni = 0; ni < 8; ni++) {
            int row = m0 + wm + mi * 16 + (lane >> 2);
            int col = n0 + wn + ni * 8 + (lane & 3) * 2;
            if (col < NE_) {  // col even, NE_ even -> col+1 < NE_ too
                float bb0 = bias[col], bb1 = bias[col + 1];
                float v0 = acc[mi][ni][0] + bb0;
                float v1 = acc[mi][ni][1] + bb1;
                float v2 = acc[mi][ni][2] + bb0;
                float v3 = acc[mi][ni][3] + bb1;
                float2 r0 = make_float2(1.f / (1.f + __expf(-v0)),
                                        1.f / (1.f + __expf(-v1)));
                float2 r1 = make_float2(1.f / (1.f + __expf(-v2)),
                                        1.f / (1.f + __expf(-v3)));
                *(float2*)(out + (size_t)row * NE_ + col) = r0;
                *(float2*)(out + (size_t)(row + 8) * NE_ + col) = r1;
            }
        }
    }
}

// ---------------- launch -----------------------------------------------------
static float* sym_addr(const void* sym) {
    void* p = nullptr;
    cudaGetSymbolAddress(&p, sym);
    return (float*)p;
}

extern "C" void kernel_launch(void* const* d_in, const int* in_sizes, int n_in,
                              void* d_out, int out_size) {
    const int*   e_s    = (const int*)d_in[0];
    const int*   q_s    = (const int*)d_in[1];
    const int*   e_c    = (const int*)d_in[2];
    const float* ent    = (const float*)d_in[3];
    const float* rel    = (const float*)d_in[4];
    const float* W1_w   = (const float*)d_in[5];
    const float* W1_b   = (const float*)d_in[6];
    const float* fc1_w  = (const float*)d_in[7];
    const float* fc1_b  = (const float*)d_in[8];
    const float* fc_w   = (const float*)d_in[9];
    const float* fc_b   = (const float*)d_in[10];
    const float* bn0_g  = (const float*)d_in[11];
    const float* bn0_b  = (const float*)d_in[12];
    const float* bn0_m  = (const float*)d_in[13];
    const float* bn0_v  = (const float*)d_in[14];
    const float* bn1_g  = (const float*)d_in[15];
    const float* bn1_b  = (const float*)d_in[16];
    const float* bn1_m  = (const float*)d_in[17];
    const float* bn1_v  = (const float*)d_in[18];
    const float* bn2_g  = (const float*)d_in[19];
    const float* bn2_b  = (const float*)d_in[20];
    const float* bn2_m  = (const float*)d_in[21];
    const float* bn2_v  = (const float*)d_in[22];
    const float* bias_b = (const float*)d_in[23];
    float* out = (float*)d_out;

    float* p_cat  = sym_addr(g_cat);
    float* p_rg   = sym_addr(g_rg);
    float* p_x    = sym_addr(g_x);
    float* p_k    = sym_addr(g_k);
    float* p_flat = sym_addr(g_flat);
    float* p_part = sym_addr(g_part);

    const int SMEM4 = 2 * 128 * LDA * (int)sizeof(__nv_bfloat16);  // 110,592 B
    cudaFuncSetAttribute(gemm4_tc, cudaFuncAttributeMaxDynamicSharedMemorySize, SMEM4);

    // 0) entity table -> bf16 padded (independent; needed only by GEMM4)
    ent2bf_kernel<<<NE_, KP>>>(ent);

    // 1) gather embeddings
    gather_kernel<<<BSZ, 256>>>(e_s, q_s, e_c, ent, rel);

    // 2) e1 = cat @ W1 + b, bn0 -> g_x   (M=1024, N=200, K=400)
    {
        dim3 g(2, 8, 1);
        gemm128<0, false><<<g, 256>>>(p_cat, W1_w, p_x, BSZ, EDIM, 400,
                                      400, EDIM, W1_b, bn0_g, bn0_v, bn0_m, bn0_b);
    }
    // 3) k = r @ fc1_w + b -> g_k        (M=1024, N=288, K=200)
    {
        dim3 g(3, 8, 1);
        gemm128<1, false><<<g, 256>>>(p_rg, fc1_w, p_k, BSZ, OCFW, EDIM,
                                      EDIM, OCFW, fc1_b, nullptr, nullptr, nullptr, nullptr);
    }
    // 4) per-sample conv + bn1 -> g_flat
    conv_kernel<<<BSZ, 192>>>(bn1_g, bn1_b, bn1_m, bn1_v);

    // 5) split-K partials of flat @ fc_w (M=1024, N=200, K=6144, 8-way split)
    {
        dim3 g(2, 8, SPLITK);
        gemm128<2, false><<<g, 256>>>(p_flat, fc_w, p_part, BSZ, EDIM, FCIN,
                                      KCH3, EDIM, nullptr, nullptr, nullptr, nullptr, nullptr);
    }
    // 6) reduce + fc_b + bn2 + relu -> g_h_bf (bf16, zero-padded to KP)
    reduce_kernel<<<BSZ, KP>>>(fc_b, bn2_g, bn2_b, bn2_m, bn2_v);

    // 7) logits = h @ ent^T + bias_b, sigmoid -> out (tensor cores)
    {
        dim3 g((NE_ + 127) / 128, 8, 1);
        gemm4_tc<<<g, 256, SMEM4>>>(bias_b, out);
    }
}

// round 3
// speedup vs baseline: 3.8219x; 2.1567x over previous
#include <cuda_runtime.h>
#include <cuda_bf16.h>
#include <math.h>

#define EPS 1e-5f

// Problem dims
#define BSZ   1024
#define EDIM  200
#define NE_   50000
#define OCFW  288     // 32*9
#define FCIN  6144    // 32*192
#define SPLITK 8

#define KP2   416     // K pad for GEMM2 (E+R=400 -> 13*32)
#define KPS   224     // K pad for 200-dim operands (7*32)
#define LDS_  40      // smem row stride in bf16 (80B) - conflict-free ldmatrix
#define STAGE_BYTES (2 * 128 * LDS_ * 2)   // A+B per stage = 20480
#define SMEM_TC (3 * STAGE_BYTES)          // 61440

typedef unsigned unt;

// ---------------- scratch ----------------------------------------------------
__device__ __align__(16) __nv_bfloat16 g_cat_bf [BSZ * KP2];
__device__ __align__(16) __nv_bfloat16 g_rg_bf  [BSZ * KPS];
__device__ float g_x   [BSZ * EDIM];
__device__ float g_k   [BSZ * OCFW];
__device__ __align__(16) __nv_bfloat16 g_flat_bf[BSZ * FCIN];
__device__ float g_part[SPLITK * BSZ * EDIM];
__device__ __align__(16) __nv_bfloat16 g_h_bf [BSZ * KPS];
__device__ __align__(16) __nv_bfloat16 g_ent_bf[(size_t)NE_ * KPS];  // 22.4MB
__device__ __align__(16) __nv_bfloat16 g_w1t [EDIM * KP2];     // [200,416]
__device__ __align__(16) __nv_bfloat16 g_fc1t[OCFW * KPS];     // [288,224]
__device__ __align__(16) __nv_bfloat16 g_fct [EDIM * FCIN];    // [200,6144]

// ---------------- tensor-core helpers ----------------------------------------
__device__ __forceinline__ void ldsm_x4(unt* r, const __nv_bfloat16* p) {
    unt addr = (unt)__cvta_generic_to_shared(p);
    asm volatile("ldmatrix.sync.aligned.m8n8.x4.shared.b16 {%0,%1,%2,%3}, [%4];"
                 : "=r"(r[0]), "=r"(r[1]), "=r"(r[2]), "=r"(r[3]) : "r"(addr));
}
__device__ __forceinline__ void mma_bf16(float* c, const unt* a, const unt* b) {
    asm volatile("mma.sync.aligned.m16n8k16.row.col.f32.bf16.bf16.f32 "
                 "{%0,%1,%2,%3},{%4,%5,%6,%7},{%8,%9},{%0,%1,%2,%3};"
                 : "+f"(c[0]), "+f"(c[1]), "+f"(c[2]), "+f"(c[3])
                 : "r"(a[0]), "r"(a[1]), "r"(a[2]), "r"(a[3]),
                   "r"(b[0]), "r"(b[1]));
}
__device__ __forceinline__ void cp16(__nv_bfloat16* dst, const __nv_bfloat16* src, bool pred) {
    unt d = (unt)__cvta_generic_to_shared(dst);
    int sz = pred ? 16 : 0;
    asm volatile("cp.async.cg.shared.global [%0], [%1], 16, %2;"
                 :: "r"(d), "l"(src), "r"(sz));
}
#define CP_COMMIT() asm volatile("cp.async.commit_group;")
#define CP_WAIT1()  asm volatile("cp.async.wait_group 1;")

// ---------------- converters --------------------------------------------------
__global__ void gather_kernel(const int* __restrict__ e_s,
                              const int* __restrict__ q_s,
                              const int* __restrict__ e_c,
                              const float* __restrict__ ent,
                              const float* __restrict__ rel) {
    int b = blockIdx.x;
    int s = e_s[b], c = e_c[b], q = q_s[b];
    int j = threadIdx.x;                      // 416 threads
    float cv = 0.f;
    if (j < EDIM)            cv = ent[(size_t)s * EDIM + j];
    else if (j < 2 * EDIM)   cv = ent[(size_t)c * EDIM + (j - EDIM)];
    g_cat_bf[b * KP2 + j] = __float2bfloat16(cv);
    if (j < KPS) {
        float rv = (j < EDIM) ? rel[(size_t)q * EDIM + j] : 0.f;
        g_rg_bf[b * KPS + j] = __float2bfloat16(rv);
    }
}

__global__ void ent2bf_kernel(const float* __restrict__ ent) {
    int t = threadIdx.x;                      // 224 threads = 2 rows x 112
    int r = blockIdx.x * 2 + t / 112;
    int c = (t % 112) * 2;
    float2 v = make_float2(0.f, 0.f);
    if (c < EDIM) v = *(const float2*)(ent + (size_t)r * EDIM + c);
    *(__nv_bfloat162*)(g_ent_bf + (size_t)r * KPS + c) = __floats2bfloat162_rn(v.x, v.y);
}

__global__ void w1t_kernel(const float* __restrict__ W1_w) {
    int n = blockIdx.x, c = threadIdx.x;      // 416
    float v = (c < 2 * EDIM) ? W1_w[c * EDIM + n] : 0.f;
    g_w1t[n * KP2 + c] = __float2bfloat16(v);
}
__global__ void fc1t_kernel(const float* __restrict__ fc1_w) {
    int n = blockIdx.x, c = threadIdx.x;      // 224
    float v = (c < EDIM) ? fc1_w[c * OCFW + n] : 0.f;
    g_fc1t[n * KPS + c] = __float2bfloat16(v);
}
__global__ void fct_kernel(const float* __restrict__ fc_w) {
    int i = blockIdx.x * 256 + threadIdx.x;   // 200*6144 total
    if (i >= EDIM * FCIN) return;
    int n = i / FCIN, c = i % FCIN;
    g_fct[i] = __float2bfloat16(fc_w[(size_t)c * EDIM + n]);
}

// ---------------- unified pipelined bf16 tensor GEMM --------------------------
// C[1024, N] = A[1024, kp] @ B[N, kp]^T   (both bf16, zero-padded K)
// MODE 0: bn0 scalar epilogue + bias; MODE 1: +bias; MODE 2: split-K partial;
// MODE 3: +bias, sigmoid.
__device__ __forceinline__ void compute_stage(const __nv_bfloat16* As,
                                              const __nv_bfloat16* Bs,
                                              int lane, int wm, int wn,
                                              float (*acc)[8][4]) {
#pragma unroll
    for (int ks = 0; ks < 2; ks++) {
        unt a[2][4];
#pragma unroll
        for (int mi = 0; mi < 2; mi++) {
            int row = wm + mi * 16 + (lane & 15);
            ldsm_x4(a[mi], As + row * LDS_ + ks * 16 + (lane >> 4) * 8);
        }
        unt b[8][2];
#pragma unroll
        for (int nj = 0; nj < 4; nj++) {
            int row = wn + nj * 16 + ((lane >> 4) & 1) * 8 + (lane & 7);
            int ko  = ks * 16 + ((lane >> 3) & 1) * 8;
            unt t[4];
            ldsm_x4(t, Bs + row * LDS_ + ko);
            b[2 * nj][0] = t[0]; b[2 * nj][1] = t[1];
            b[2 * nj + 1][0] = t[2]; b[2 * nj + 1][1] = t[3];
        }
#pragma unroll
        for (int mi = 0; mi < 2; mi++)
#pragma unroll
            for (int ni = 0; ni < 8; ni++)
                mma_bf16(acc[mi][ni], a[mi], b[ni]);
    }
}

template<int MODE>
__global__ __launch_bounds__(256, 2)
void gemm_tc(const __nv_bfloat16* __restrict__ A, const __nv_bfloat16* __restrict__ B,
             float* __restrict__ C, int N, int kp, int kiters, int ldc,
             const float* __restrict__ bias,
             const float* __restrict__ p0, const float* __restrict__ p1,
             const float* __restrict__ p2, const float* __restrict__ p3) {
    extern __shared__ char sm[];
    const int tid = threadIdx.x;
    const int m0 = blockIdx.y * 128;
    const int n0 = blockIdx.x * 128;
    const int kbase = blockIdx.z * kiters;    // in units of 32

    // stage loader: A tile 128x32, B tile 128x32, 16B chunks
    auto load_stage = [&](int kb, int stage) {
        __nv_bfloat16* As = (__nv_bfloat16*)(sm + stage * STAGE_BYTES);
        __nv_bfloat16* Bs = As + 128 * LDS_;
#pragma unroll
        for (int j = 0; j < 2; j++) {
            int i = tid + j * 256;
            int r = i >> 2, c = (i & 3) * 8;
            cp16(As + r * LDS_ + c, A + (size_t)(m0 + r) * kp + kb * 32 + c, true);
            bool pn = (n0 + r) < N;
            const __nv_bfloat16* bs = pn ? (B + (size_t)(n0 + r) * kp + kb * 32 + c) : B;
            cp16(Bs + r * LDS_ + c, bs, pn);
        }
    };

    load_stage(kbase + 0, 0); CP_COMMIT();
    load_stage(kbase + 1, 1); CP_COMMIT();

    const int lane = tid & 31, wid = tid >> 5;
    const int wm = (wid & 3) * 32;
    const int wn = (wid >> 2) * 64;

    float acc[2][8][4];
#pragma unroll
    for (int i = 0; i < 2; i++)
#pragma unroll
        for (int j = 0; j < 8; j++)
#pragma unroll
            for (int l = 0; l < 4; l++) acc[i][j][l] = 0.f;

    for (int kb = 0; kb < kiters; kb++) {
        CP_WAIT1();
        __syncthreads();
        if (kb + 2 < kiters) load_stage(kbase + kb + 2, (kb + 2) % 3);
        CP_COMMIT();
        int st = kb % 3;
        compute_stage((__nv_bfloat16*)(sm + st * STAGE_BYTES),
                      (__nv_bfloat16*)(sm + st * STAGE_BYTES) + 128 * LDS_,
                      lane, wm, wn, acc);
        __syncthreads();
    }

    // ---- epilogue
    float sc0 = 1.f, sm0 = 0.f, sb0 = 0.f;
    if (MODE == 0) {
        sc0 = p0[0] * rsqrtf(p1[0] + EPS);
        sm0 = p2[0];
        sb0 = p3[0];
    }
    size_t rowbase = (MODE == 2) ? (size_t)blockIdx.z * BSZ : 0;
#pragma unroll
    for (int mi = 0; mi < 2; mi++) {
#pragma unroll
        for (int ni = 0; ni < 8; ni++) {
            int row = m0 + wm + mi * 16 + (lane >> 2);
            int col = n0 + wn + ni * 8 + (lane & 3) * 2;
            if (col < N) {   // col even, N even -> col+1 valid too
                float v0 = acc[mi][ni][0];
                float v1 = acc[mi][ni][1];
                float v2 = acc[mi][ni][2];
                float v3 = acc[mi][ni][3];
                if (MODE != 2) {
                    float bb0 = bias[col], bb1 = bias[col + 1];
                    v0 += bb0; v1 += bb1; v2 += bb0; v3 += bb1;
                }
                if (MODE == 0) {
                    v0 = (v0 - sm0) * sc0 + sb0; v1 = (v1 - sm0) * sc0 + sb0;
                    v2 = (v2 - sm0) * sc0 + sb0; v3 = (v3 - sm0) * sc0 + sb0;
                } else if (MODE == 3) {
                    v0 = 1.f / (1.f + __expf(-v0)); v1 = 1.f / (1.f + __expf(-v1));
                    v2 = 1.f / (1.f + __expf(-v2)); v3 = 1.f / (1.f + __expf(-v3));
                }
                *(float2*)(C + (rowbase + row) * (size_t)ldc + col)       = make_float2(v0, v1);
                *(float2*)(C + (rowbase + row + 8) * (size_t)ldc + col)   = make_float2(v2, v3);
            }
        }
    }
}

// ---------------- per-sample dynamic conv + bn1 -> bf16 flat ------------------
__global__ void conv_kernel(const float* __restrict__ bn1_g,
                            const float* __restrict__ bn1_b,
                            const float* __restrict__ bn1_m,
                            const float* __restrict__ bn1_v) {
    int b = blockIdx.x;
    __shared__ float xs[EDIM];
    __shared__ float ks[OCFW];
    __shared__ float sc[32], sh[32];
    int t = threadIdx.x; // 192
    for (int j = t; j < EDIM; j += 192) xs[j] = g_x[b * EDIM + j];
    for (int j = t; j < OCFW; j += 192) ks[j] = g_k[b * OCFW + j];
    if (t < 32) {
        float s = bn1_g[t] * rsqrtf(bn1_v[t] + EPS);
        sc[t] = s;
        sh[t] = bn1_b[t] - bn1_m[t] * s;
    }
    __syncthreads();
    int p = t;
    float xv[9];
#pragma unroll
    for (int w = 0; w < 9; w++) xv[w] = xs[p + w];
    __nv_bfloat16* outrow = &g_flat_bf[(size_t)b * FCIN];
#pragma unroll 4
    for (int oc = 0; oc < 32; oc++) {
        float s = 0.f;
#pragma unroll
        for (int w = 0; w < 9; w++) s += xv[w] * ks[oc * 9 + w];
        outrow[oc * 192 + p] = __float2bfloat16(s * sc[oc] + sh[oc]);
    }
}

// ---------------- split-K reduce + fc bias + bn2 + relu -> bf16 h -------------
__global__ void reduce_kernel(const float* __restrict__ fc_b,
                              const float* __restrict__ g2,
                              const float* __restrict__ b2,
                              const float* __restrict__ m2,
                              const float* __restrict__ v2) {
    int b = blockIdx.x;
    int n = threadIdx.x;       // 224
    float r = 0.f;
    if (n < EDIM) {
        float s = fc_b[n];
        int idx = b * EDIM + n;
#pragma unroll
        for (int z = 0; z < SPLITK; z++) s += g_part[(size_t)z * BSZ * EDIM + idx];
        float sc = g2[n] * rsqrtf(v2[n] + EPS);
        s = (s - m2[n]) * sc + b2[n];
        r = fmaxf(s, 0.f);
    }
    g_h_bf[b * KPS + n] = __float2bfloat16(r);
}

// ---------------- launch -------------------------------------------------------
template<typename T>
static T* sym_addr(const void* sym) {
    void* p = nullptr;
    cudaGetSymbolAddress(&p, sym);
    return (T*)p;
}

extern "C" void kernel_launch(void* const* d_in, const int* in_sizes, int n_in,
                              void* d_out, int out_size) {
    const int*   e_s    = (const int*)d_in[0];
    const int*   q_s    = (const int*)d_in[1];
    const int*   e_c    = (const int*)d_in[2];
    const float* ent    = (const float*)d_in[3];
    const float* rel    = (const float*)d_in[4];
    const float* W1_w   = (const float*)d_in[5];
    const float* W1_b   = (const float*)d_in[6];
    const float* fc1_w  = (const float*)d_in[7];
    const float* fc1_b  = (const float*)d_in[8];
    const float* fc_w   = (const float*)d_in[9];
    const float* fc_b   = (const float*)d_in[10];
    const float* bn0_g  = (const float*)d_in[11];
    const float* bn0_b  = (const float*)d_in[12];
    const float* bn0_m  = (const float*)d_in[13];
    const float* bn0_v  = (const float*)d_in[14];
    const float* bn1_g  = (const float*)d_in[15];
    const float* bn1_b  = (const float*)d_in[16];
    const float* bn1_m  = (const float*)d_in[17];
    const float* bn1_v  = (const float*)d_in[18];
    const float* bn2_g  = (const float*)d_in[19];
    const float* bn2_b  = (const float*)d_in[20];
    const float* bn2_m  = (const float*)d_in[21];
    const float* bn2_v  = (const float*)d_in[22];
    const float* bias_b = (const float*)d_in[23];
    float* out = (float*)d_out;

    __nv_bfloat16* p_cat  = sym_addr<__nv_bfloat16>(g_cat_bf);
    __nv_bfloat16* p_rg   = sym_addr<__nv_bfloat16>(g_rg_bf);
    __nv_bfloat16* p_flat = sym_addr<__nv_bfloat16>(g_flat_bf);
    __nv_bfloat16* p_hbf  = sym_addr<__nv_bfloat16>(g_h_bf);
    __nv_bfloat16* p_entb = sym_addr<__nv_bfloat16>(g_ent_bf);
    __nv_bfloat16* p_w1t  = sym_addr<__nv_bfloat16>(g_w1t);
    __nv_bfloat16* p_fc1t = sym_addr<__nv_bfloat16>(g_fc1t);
    __nv_bfloat16* p_fct  = sym_addr<__nv_bfloat16>(g_fct);
    float* p_x    = sym_addr<float>(g_x);
    float* p_k    = sym_addr<float>(g_k);
    float* p_part = sym_addr<float>(g_part);

    cudaFuncSetAttribute(gemm_tc<0>, cudaFuncAttributeMaxDynamicSharedMemorySize, SMEM_TC);
    cudaFuncSetAttribute(gemm_tc<1>, cudaFuncAttributeMaxDynamicSharedMemorySize, SMEM_TC);
    cudaFuncSetAttribute(gemm_tc<2>, cudaFuncAttributeMaxDynamicSharedMemorySize, SMEM_TC);
    cudaFuncSetAttribute(gemm_tc<3>, cudaFuncAttributeMaxDynamicSharedMemorySize, SMEM_TC);

    // converters (weights + entity table)
    ent2bf_kernel<<<NE_ / 2, 224>>>(ent);
    w1t_kernel<<<EDIM, KP2>>>(W1_w);
    fc1t_kernel<<<OCFW, KPS>>>(fc1_w);
    fct_kernel<<<(EDIM * FCIN + 255) / 256, 256>>>(fc_w);

    // 1) gather -> bf16 cat / r
    gather_kernel<<<BSZ, KP2>>>(e_s, q_s, e_c, ent, rel);

    // 2) e1 = cat @ W1 + b, bn0 -> g_x (fp32)
    {
        dim3 g(2, 8, 1);
        gemm_tc<0><<<g, 256, SMEM_TC>>>(p_cat, p_w1t, p_x, EDIM, KP2, KP2 / 32, EDIM,
                                        W1_b, bn0_g, bn0_v, bn0_m, bn0_b);
    }
    // 3) k = r @ fc1_w + b -> g_k (fp32)
    {
        dim3 g(3, 8, 1);
        gemm_tc<1><<<g, 256, SMEM_TC>>>(p_rg, p_fc1t, p_k, OCFW, KPS, KPS / 32, OCFW,
                                        fc1_b, nullptr, nullptr, nullptr, nullptr);
    }
    // 4) per-sample conv + bn1 -> g_flat_bf
    conv_kernel<<<BSZ, 192>>>(bn1_g, bn1_b, bn1_m, bn1_v);

    // 5) split-K partials of flat @ fc_w
    {
        dim3 g(2, 8, SPLITK);
        gemm_tc<2><<<g, 256, SMEM_TC>>>(p_flat, p_fct, p_part, EDIM, FCIN,
                                        FCIN / 32 / SPLITK, EDIM,
                                        nullptr, nullptr, nullptr, nullptr, nullptr);
    }
    // 6) reduce + fc_b + bn2 + relu -> g_h_bf
    reduce_kernel<<<BSZ, KPS>>>(fc_b, bn2_g, bn2_b, bn2_m, bn2_v);

    // 7) logits = h @ ent^T + bias_b, sigmoid -> out
    {
        dim3 g((NE_ + 127) / 128, 8, 1);
        gemm_tc<3><<<g, 256, SMEM_TC>>>(p_hbf, p_entb, out, NE_, KPS, KPS / 32, NE_,
                                        bias_b, nullptr, nullptr, nullptr, nullptr);
    }
}

// round 5
// speedup vs baseline: 4.5623x; 1.1937x over previous
#include <cuda_runtime.h>
#include <cuda_bf16.h>
#include <math.h>
#include <cstdint>

#define EPS 1e-5f

// Problem dims
#define BSZ   1024
#define EDIM  200
#define NE_   50000
#define OCFW  288     // 32*9
#define FCIN  6144    // 32*192
#define SPLITK 8

#define KP2   416     // K pad for GEMM2 (E+R=400 -> 13*32)
#define KPS   224     // K pad for 200-dim operands (7*32)
#define LDS_  40      // smem row stride bf16 (80B) - conflict-free ldmatrix
#define STAGE_BYTES (2 * 128 * LDS_ * 2)   // A+B per stage = 20480
#define SMEM_TC (3 * STAGE_BYTES)          // 61440

// GEMM4 (A-resident) smem layout
#define A4_STR 232                          // bf16 stride; 232*2=464B -> conflict-free
#define SM4A   (128 * A4_STR * 2)           // 59392
#define SM4B_STAGE (128 * LDS_ * 2)         // 10240
#define SM4_TOTAL (SM4A + 3 * SM4B_STAGE)   // 90112

typedef unsigned unt;

// ---------------- scratch ----------------------------------------------------
__device__ __align__(16) __nv_bfloat16 g_cat_bf [BSZ * KP2];
__device__ __align__(16) __nv_bfloat16 g_rg_bf  [BSZ * KPS];
__device__ float g_x   [BSZ * EDIM];
__device__ float g_k   [BSZ * OCFW];
__device__ __align__(16) __nv_bfloat16 g_flat_bf[BSZ * FCIN];
__device__ float g_part[SPLITK * BSZ * EDIM];
__device__ __align__(16) __nv_bfloat16 g_h_bf [BSZ * KPS];
__device__ __align__(16) __nv_bfloat16 g_ent_bf[(size_t)NE_ * KPS];  // 22.4MB
__device__ __align__(16) __nv_bfloat16 g_w1t [EDIM * KP2];
__device__ __align__(16) __nv_bfloat16 g_fc1t[OCFW * KPS];
__device__ __align__(16) __nv_bfloat16 g_fct [EDIM * FCIN];

// ---------------- asm helpers --------------------------------------------------
__device__ __forceinline__ unt smem_u32(const void* p) {
    unt a;
    asm("{ .reg .u64 t; cvta.to.shared.u64 t, %1; cvt.u32.u64 %0, t; }"
        : "=r"(a) : "l"(p));
    return a;
}
__device__ __forceinline__ void ldsm_x4(unt* r, const __nv_bfloat16* p) {
    unt addr = smem_u32(p);
    asm volatile("ldmatrix.sync.aligned.m8n8.x4.shared.b16 {%0,%1,%2,%3}, [%4];"
                 : "=r"(r[0]), "=r"(r[1]), "=r"(r[2]), "=r"(r[3]) : "r"(addr));
}
__device__ __forceinline__ void mma_bf16(float* c, const unt* a, const unt* b) {
    asm volatile("mma.sync.aligned.m16n8k16.row.col.f32.bf16.bf16.f32 "
                 "{%0,%1,%2,%3},{%4,%5,%6,%7},{%8,%9},{%0,%1,%2,%3};"
                 : "+f"(c[0]), "+f"(c[1]), "+f"(c[2]), "+f"(c[3])
                 : "r"(a[0]), "r"(a[1]), "r"(a[2]), "r"(a[3]),
                   "r"(b[0]), "r"(b[1]));
}
__device__ __forceinline__ void cp16p(__nv_bfloat16* dst, const __nv_bfloat16* src, bool pred) {
    unt d = smem_u32(dst);
    int sz = pred ? 16 : 0;
    asm volatile("cp.async.cg.shared.global [%0], [%1], 16, %2;"
                 :: "r"(d), "l"(src), "r"(sz));
}
#define CP_COMMIT() asm volatile("cp.async.commit_group;")
#define CP_WAIT1()  asm volatile("cp.async.wait_group 1;")

__device__ __forceinline__ float sigf(float x) {
    float e, r;
    asm("ex2.approx.f32 %0, %1;" : "=f"(e) : "f"(-1.44269504f * x));
    asm("rcp.approx.f32 %0, %1;" : "=f"(r) : "f"(1.f + e));
    return r;
}

// ---------------- converters --------------------------------------------------
__global__ void gather_kernel(const int* __restrict__ e_s,
                              const int* __restrict__ q_s,
                              const int* __restrict__ e_c,
                              const float* __restrict__ ent,
                              const float* __restrict__ rel) {
    int b = blockIdx.x;
    int s = e_s[b], c = e_c[b], q = q_s[b];
    int j = threadIdx.x;                      // 416 threads
    float cv = 0.f;
    if (j < EDIM)            cv = ent[(size_t)s * EDIM + j];
    else if (j < 2 * EDIM)   cv = ent[(size_t)c * EDIM + (j - EDIM)];
    g_cat_bf[b * KP2 + j] = __float2bfloat16(cv);
    if (j < KPS) {
        float rv = (j < EDIM) ? rel[(size_t)q * EDIM + j] : 0.f;
        g_rg_bf[b * KPS + j] = __float2bfloat16(rv);
    }
}

// vectorized fp32 -> bf16 entity table, padded to KPS
__global__ void ent2bf_kernel(const float* __restrict__ ent) {
    int idx = blockIdx.x * 256 + threadIdx.x;
    if (idx >= NE_ * 56) return;
    int r = idx / 56, q = idx % 56;           // quads of 4 elems; 56*4 = 224
    float4 v = make_float4(0.f, 0.f, 0.f, 0.f);
    if (q < 50) v = *(const float4*)(ent + (size_t)r * EDIM + q * 4);
    __nv_bfloat162 lo = __floats2bfloat162_rn(v.x, v.y);
    __nv_bfloat162 hi = __floats2bfloat162_rn(v.z, v.w);
    uint2 pk;
    pk.x = *(unt*)&lo; pk.y = *(unt*)&hi;
    *(uint2*)(g_ent_bf + (size_t)r * KPS + q * 4) = pk;
}

__global__ void w1t_kernel(const float* __restrict__ W1_w) {
    int n = blockIdx.x, c = threadIdx.x;      // 416
    float v = (c < 2 * EDIM) ? W1_w[c * EDIM + n] : 0.f;
    g_w1t[n * KP2 + c] = __float2bfloat16(v);
}
__global__ void fc1t_kernel(const float* __restrict__ fc1_w) {
    int n = blockIdx.x, c = threadIdx.x;      // 224
    float v = (c < EDIM) ? fc1_w[c * OCFW + n] : 0.f;
    g_fc1t[n * KPS + c] = __float2bfloat16(v);
}
// transpose fc_w [6144,200] -> g_fct [200,6144] via smem tiles
__global__ void fct_kernel(const float* __restrict__ fc_w) {
    __shared__ float tile[32][33];
    int tx = threadIdx.x & 31, ty = threadIdx.x >> 5;   // 256 = 32x8
    int cbase = blockIdx.x * 32;   // over FCIN
    int nbase = blockIdx.y * 32;   // over EDIM
#pragma unroll
    for (int j = 0; j < 4; j++) {
        int cc = cbase + ty + j * 8;
        int nn = nbase + tx;
        tile[ty + j * 8][tx] = (nn < EDIM) ? fc_w[(size_t)cc * EDIM + nn] : 0.f;
    }
    __syncthreads();
#pragma unroll
    for (int j = 0; j < 4; j++) {
        int nn = nbase + ty + j * 8;
        int cc = cbase + tx;
        if (nn < EDIM)
            g_fct[(size_t)nn * FCIN + cc] = __float2bfloat16(tile[tx][ty + j * 8]);
    }
}

// ---------------- mma.sync compute core ----------------------------------------
__device__ __forceinline__ void compute_stage(const __nv_bfloat16* As, int astr, int ak0,
                                              const __nv_bfloat16* Bs,
                                              int lane, int wm, int wn,
                                              float (*acc)[8][4]) {
#pragma unroll
    for (int ks = 0; ks < 2; ks++) {
        unt a[2][4];
#pragma unroll
        for (int mi = 0; mi < 2; mi++) {
            int row = wm + mi * 16 + (lane & 15);
            ldsm_x4(a[mi], As + row * astr + ak0 + ks * 16 + (lane >> 4) * 8);
        }
        unt b[8][2];
#pragma unroll
        for (int nj = 0; nj < 4; nj++) {
            int row = wn + nj * 16 + ((lane >> 4) & 1) * 8 + (lane & 7);
            int ko  = ks * 16 + ((lane >> 3) & 1) * 8;
            unt t[4];
            ldsm_x4(t, Bs + row * LDS_ + ko);
            b[2 * nj][0] = t[0]; b[2 * nj][1] = t[1];
            b[2 * nj + 1][0] = t[2]; b[2 * nj + 1][1] = t[3];
        }
#pragma unroll
        for (int mi = 0; mi < 2; mi++)
#pragma unroll
            for (int ni = 0; ni < 8; ni++)
                mma_bf16(acc[mi][ni], a[mi], b[ni]);
    }
}

// ---------------- pipelined GEMM for small GEMMs (modes 0/1/2) -----------------
template<int MODE>
__global__ __launch_bounds__(256, 2)
void gemm_tc(const __nv_bfloat16* __restrict__ A, const __nv_bfloat16* __restrict__ B,
             float* __restrict__ C, int N, int kp, int kiters, int ldc,
             const float* __restrict__ bias,
             const float* __restrict__ p0, const float* __restrict__ p1,
             const float* __restrict__ p2, const float* __restrict__ p3) {
    extern __shared__ char sm[];
    const int tid = threadIdx.x;
    const int m0 = blockIdx.y * 128;
    const int n0 = blockIdx.x * 128;
    const int kbase = blockIdx.z * kiters;

    auto load_stage = [&](int kb, int stage) {
        __nv_bfloat16* As = (__nv_bfloat16*)(sm + stage * STAGE_BYTES);
        __nv_bfloat16* Bs = As + 128 * LDS_;
#pragma unroll
        for (int j = 0; j < 2; j++) {
            int i = tid + j * 256;
            int r = i >> 2, c = (i & 3) * 8;
            cp16p(As + r * LDS_ + c, A + (size_t)(m0 + r) * kp + kb * 32 + c, true);
            bool pn = (n0 + r) < N;
            const __nv_bfloat16* bs = pn ? (B + (size_t)(n0 + r) * kp + kb * 32 + c) : B;
            cp16p(Bs + r * LDS_ + c, bs, pn);
        }
    };

    load_stage(kbase + 0, 0); CP_COMMIT();
    load_stage(kbase + 1, 1); CP_COMMIT();

    const int lane = tid & 31, wid = tid >> 5;
    const int wm = (wid & 3) * 32;
    const int wn = (wid >> 2) * 64;

    float acc[2][8][4];
#pragma unroll
    for (int i = 0; i < 2; i++)
#pragma unroll
        for (int j = 0; j < 8; j++)
#pragma unroll
            for (int l = 0; l < 4; l++) acc[i][j][l] = 0.f;

    for (int kb = 0; kb < kiters; kb++) {
        CP_WAIT1();
        __syncthreads();
        if (kb + 2 < kiters) load_stage(kbase + kb + 2, (kb + 2) % 3);
        CP_COMMIT();
        int st = kb % 3;
        const __nv_bfloat16* As = (const __nv_bfloat16*)(sm + st * STAGE_BYTES);
        compute_stage(As, LDS_, 0, As + 128 * LDS_, lane, wm, wn, acc);
        __syncthreads();
    }

    float sc0 = 1.f, sm0 = 0.f, sb0 = 0.f;
    if (MODE == 0) {
        sc0 = p0[0] * rsqrtf(p1[0] + EPS);
        sm0 = p2[0];
        sb0 = p3[0];
    }
    size_t rowbase = (MODE == 2) ? (size_t)blockIdx.z * BSZ : 0;
#pragma unroll
    for (int mi = 0; mi < 2; mi++) {
#pragma unroll
        for (int ni = 0; ni < 8; ni++) {
            int row = m0 + wm + mi * 16 + (lane >> 2);
            int col = n0 + wn + ni * 8 + (lane & 3) * 2;
            if (col < N) {
                float v0 = acc[mi][ni][0];
                float v1 = acc[mi][ni][1];
                float v2 = acc[mi][ni][2];
                float v3 = acc[mi][ni][3];
                if (MODE != 2) {
                    float bb0 = bias[col], bb1 = bias[col + 1];
                    v0 += bb0; v1 += bb1; v2 += bb0; v3 += bb1;
                }
                if (MODE == 0) {
                    v0 = (v0 - sm0) * sc0 + sb0; v1 = (v1 - sm0) * sc0 + sb0;
                    v2 = (v2 - sm0) * sc0 + sb0; v3 = (v3 - sm0) * sc0 + sb0;
                }
                *(float2*)(C + (rowbase + row) * (size_t)ldc + col)     = make_float2(v0, v1);
                *(float2*)(C + (rowbase + row + 8) * (size_t)ldc + col) = make_float2(v2, v3);
            }
        }
    }
}

// ---------------- GEMM4: A-resident, B-pipelined, bias+sigmoid -----------------
__global__ __launch_bounds__(256, 2)
void gemm4_ms(const float* __restrict__ bias, float* __restrict__ out) {
    extern __shared__ char sm[];
    __nv_bfloat16* Asm = (__nv_bfloat16*)sm;
    const int tid = threadIdx.x;
    const int m0 = blockIdx.y * 128;
    const int n0 = blockIdx.x * 128;

    // load full A stripe 128 x 224 (resident)
    for (int i = tid; i < 3584; i += 256) {
        int r = i / 28, c = (i % 28) * 8;
        cp16p(Asm + r * A4_STR + c, g_h_bf + (size_t)(m0 + r) * KPS + c, true);
    }
    CP_COMMIT();

    auto loadB = [&](int kb, int st) {
        __nv_bfloat16* Bs = (__nv_bfloat16*)(sm + SM4A + st * SM4B_STAGE);
#pragma unroll
        for (int j = 0; j < 2; j++) {
            int i = tid + j * 256;
            int r = i >> 2, c = (i & 3) * 8;
            bool pn = (n0 + r) < NE_;
            const __nv_bfloat16* src =
                pn ? (g_ent_bf + (size_t)(n0 + r) * KPS + kb * 32 + c) : g_ent_bf;
            cp16p(Bs + r * LDS_ + c, src, pn);
        }
    };
    loadB(0, 0); CP_COMMIT();
    loadB(1, 1); CP_COMMIT();

    const int lane = tid & 31, wid = tid >> 5;
    const int wm = (wid & 3) * 32;
    const int wn = (wid >> 2) * 64;

    float acc[2][8][4];
#pragma unroll
    for (int i = 0; i < 2; i++)
#pragma unroll
        for (int j = 0; j < 8; j++)
#pragma unroll
            for (int l = 0; l < 4; l++) acc[i][j][l] = 0.f;

#pragma unroll
    for (int kb = 0; kb < 7; kb++) {
        CP_WAIT1();
        __syncthreads();
        if (kb + 2 < 7) loadB(kb + 2, (kb + 2) % 3);
        CP_COMMIT();
        const __nv_bfloat16* Bs =
            (const __nv_bfloat16*)(sm + SM4A + (kb % 3) * SM4B_STAGE);
        compute_stage(Asm, A4_STR, kb * 32, Bs, lane, wm, wn, acc);
        __syncthreads();
    }

    // epilogue: + bias, sigmoid, store
#pragma unroll
    for (int mi = 0; mi < 2; mi++) {
#pragma unroll
        for (int ni = 0; ni < 8; ni++) {
            int row = m0 + wm + mi * 16 + (lane >> 2);
            int col = n0 + wn + ni * 8 + (lane & 3) * 2;
            if (col < NE_) {   // col even, NE_ even -> col+1 valid too
                float bb0 = bias[col], bb1 = bias[col + 1];
                float v0 = sigf(acc[mi][ni][0] + bb0);
                float v1 = sigf(acc[mi][ni][1] + bb1);
                float v2 = sigf(acc[mi][ni][2] + bb0);
                float v3 = sigf(acc[mi][ni][3] + bb1);
                *(float2*)(out + (size_t)row * NE_ + col)       = make_float2(v0, v1);
                *(float2*)(out + (size_t)(row + 8) * NE_ + col) = make_float2(v2, v3);
            }
        }
    }
}

// ---------------- per-sample dynamic conv + bn1 -> bf16 flat ------------------
__global__ void conv_kernel(const float* __restrict__ bn1_g,
                            const float* __restrict__ bn1_b,
                            const float* __restrict__ bn1_m,
                            const float* __restrict__ bn1_v) {
    int b = blockIdx.x;
    __shared__ float xs[EDIM];
    __shared__ float ks[OCFW];
    __shared__ float sc[32], sh[32];
    int t = threadIdx.x; // 192
    for (int j = t; j < EDIM; j += 192) xs[j] = g_x[b * EDIM + j];
    for (int j = t; j < OCFW; j += 192) ks[j] = g_k[b * OCFW + j];
    if (t < 32) {
        float s = bn1_g[t] * rsqrtf(bn1_v[t] + EPS);
        sc[t] = s;
        sh[t] = bn1_b[t] - bn1_m[t] * s;
    }
    __syncthreads();
    int p = t;
    float xv[9];
#pragma unroll
    for (int w = 0; w < 9; w++) xv[w] = xs[p + w];
    __nv_bfloat16* outrow = &g_flat_bf[(size_t)b * FCIN];
#pragma unroll 4
    for (int oc = 0; oc < 32; oc++) {
        float s = 0.f;
#pragma unroll
        for (int w = 0; w < 9; w++) s += xv[w] * ks[oc * 9 + w];
        outrow[oc * 192 + p] = __float2bfloat16(s * sc[oc] + sh[oc]);
    }
}

// ---------------- split-K reduce + fc bias + bn2 + relu -> bf16 h -------------
__global__ void reduce_kernel(const float* __restrict__ fc_b,
                              const float* __restrict__ g2,
                              const float* __restrict__ b2,
                              const float* __restrict__ m2,
                              const float* __restrict__ v2) {
    int b = blockIdx.x;
    int n = threadIdx.x;       // 224
    float r = 0.f;
    if (n < EDIM) {
        float s = fc_b[n];
        int idx = b * EDIM + n;
#pragma unroll
        for (int z = 0; z < SPLITK; z++) s += g_part[(size_t)z * BSZ * EDIM + idx];
        float sc = g2[n] * rsqrtf(v2[n] + EPS);
        s = (s - m2[n]) * sc + b2[n];
        r = fmaxf(s, 0.f);
    }
    g_h_bf[b * KPS + n] = __float2bfloat16(r);
}

// ---------------- launch -------------------------------------------------------
template<typename T>
static T* sym_addr(const void* sym) {
    void* p = nullptr;
    cudaGetSymbolAddress(&p, sym);
    return (T*)p;
}

extern "C" void kernel_launch(void* const* d_in, const int* in_sizes, int n_in,
                              void* d_out, int out_size) {
    const int*   e_s    = (const int*)d_in[0];
    const int*   q_s    = (const int*)d_in[1];
    const int*   e_c    = (const int*)d_in[2];
    const float* ent    = (const float*)d_in[3];
    const float* rel    = (const float*)d_in[4];
    const float* W1_w   = (const float*)d_in[5];
    const float* W1_b   = (const float*)d_in[6];
    const float* fc1_w  = (const float*)d_in[7];
    const float* fc1_b  = (const float*)d_in[8];
    const float* fc_w   = (const float*)d_in[9];
    const float* fc_b   = (const float*)d_in[10];
    const float* bn0_g  = (const float*)d_in[11];
    const float* bn0_b  = (const float*)d_in[12];
    const float* bn0_m  = (const float*)d_in[13];
    const float* bn0_v  = (const float*)d_in[14];
    const float* bn1_g  = (const float*)d_in[15];
    const float* bn1_b  = (const float*)d_in[16];
    const float* bn1_m  = (const float*)d_in[17];
    const float* bn1_v  = (const float*)d_in[18];
    const float* bn2_g  = (const float*)d_in[19];
    const float* bn2_b  = (const float*)d_in[20];
    const float* bn2_m  = (const float*)d_in[21];
    const float* bn2_v  = (const float*)d_in[22];
    const float* bias_b = (const float*)d_in[23];
    float* out = (float*)d_out;

    __nv_bfloat16* p_cat  = sym_addr<__nv_bfloat16>(g_cat_bf);
    __nv_bfloat16* p_rg   = sym_addr<__nv_bfloat16>(g_rg_bf);
    __nv_bfloat16* p_flat = sym_addr<__nv_bfloat16>(g_flat_bf);
    __nv_bfloat16* p_w1t  = sym_addr<__nv_bfloat16>(g_w1t);
    __nv_bfloat16* p_fc1t = sym_addr<__nv_bfloat16>(g_fc1t);
    __nv_bfloat16* p_fct  = sym_addr<__nv_bfloat16>(g_fct);
    float* p_x    = sym_addr<float>(g_x);
    float* p_k    = sym_addr<float>(g_k);
    float* p_part = sym_addr<float>(g_part);

    cudaFuncSetAttribute(gemm_tc<0>, cudaFuncAttributeMaxDynamicSharedMemorySize, SMEM_TC);
    cudaFuncSetAttribute(gemm_tc<1>, cudaFuncAttributeMaxDynamicSharedMemorySize, SMEM_TC);
    cudaFuncSetAttribute(gemm_tc<2>, cudaFuncAttributeMaxDynamicSharedMemorySize, SMEM_TC);
    cudaFuncSetAttribute(gemm4_ms, cudaFuncAttributeMaxDynamicSharedMemorySize, SM4_TOTAL);

    // converters
    ent2bf_kernel<<<(NE_ * 56 + 255) / 256, 256>>>(ent);
    w1t_kernel<<<EDIM, KP2>>>(W1_w);
    fc1t_kernel<<<OCFW, KPS>>>(fc1_w);
    {
        dim3 g(FCIN / 32, (EDIM + 31) / 32);
        fct_kernel<<<g, 256>>>(fc_w);
    }

    // 1) gather -> bf16 cat / r
    gather_kernel<<<BSZ, KP2>>>(e_s, q_s, e_c, ent, rel);

    // 2) e1 = cat @ W1 + b, bn0 -> g_x (fp32)
    {
        dim3 g(2, 8, 1);
        gemm_tc<0><<<g, 256, SMEM_TC>>>(p_cat, p_w1t, p_x, EDIM, KP2, KP2 / 32, EDIM,
                                        W1_b, bn0_g, bn0_v, bn0_m, bn0_b);
    }
    // 3) k = r @ fc1_w + b -> g_k (fp32)
    {
        dim3 g(3, 8, 1);
        gemm_tc<1><<<g, 256, SMEM_TC>>>(p_rg, p_fc1t, p_k, OCFW, KPS, KPS / 32, OCFW,
                                        fc1_b, nullptr, nullptr, nullptr, nullptr);
    }
    // 4) per-sample conv + bn1 -> g_flat_bf
    conv_kernel<<<BSZ, 192>>>(bn1_g, bn1_b, bn1_m, bn1_v);

    // 5) split-K partials of flat @ fc_w
    {
        dim3 g(2, 8, SPLITK);
        gemm_tc<2><<<g, 256, SMEM_TC>>>(p_flat, p_fct, p_part, EDIM, FCIN,
                                        FCIN / 32 / SPLITK, EDIM,
                                        nullptr, nullptr, nullptr, nullptr, nullptr);
    }
    // 6) reduce + fc_b + bn2 + relu -> g_h_bf (bf16, zero-padded to 224)
    reduce_kernel<<<BSZ, KPS>>>(fc_b, bn2_g, bn2_b, bn2_m, bn2_v);

    // 7) logits = h @ ent^T + bias_b, sigmoid -> out (A-resident mma.sync)
    {
        dim3 g((NE_ + 127) / 128, 8, 1);
        gemm4_ms<<<g, 256, SM4_TOTAL>>>(bias_b, out);
    }
}